// round 15
// baseline (speedup 1.0000x reference)
#include <cuda_runtime.h>
#include <cuda_bf16.h>
#include <cstdint>

#define H_DIM 4096
#define I_DIM 11008
#define B_DIM 64
#define QGROUP 128
#define GU_SPLIT 5
#define DN_SPLIT 9

// ---------------------------------------------------------------------------
// Scratch (no device allocation allowed anywhere).
// X/h activations pre-converted to tf32 bits in the exact smem tile image:
// [ktile][64 rows][72 words], pair-permuted within 8-col groups.
// ---------------------------------------------------------------------------
__device__ uint32_t g_xt[(H_DIM / 64) * 64 * 72];       // x as tf32 tiles (1.2 MB)
__device__ uint32_t g_ht[(I_DIM / 64) * 64 * 72];       // h as tf32 tiles (3.2 MB)
__device__ float g_pg[GU_SPLIT * B_DIM * I_DIM];        // gate split-K partials
__device__ float g_pu[GU_SPLIT * B_DIM * I_DIM];        // up   split-K partials
__device__ float g_pd[DN_SPLIT * B_DIM * H_DIM];        // down split-K partials

#define TX_WORDS (64 * 72)                  // X tile (64 batch rows)
#define TW_WORDS (128 * 72)                 // W tile (128 output rows)
#define SMEM_BYTES ((2 * TX_WORDS + 2 * TW_WORDS) * 4)   // 110592 -> occ 2

__device__ __forceinline__ uint32_t f2tf32(float f) {
    uint32_t r;
    asm("cvt.rna.tf32.f32 %0, %1;" : "=r"(r) : "f"(f));
    return r;
}

// permuted position of col c (0..7) within an 8-word k-group: [0,4,1,5,2,6,3,7]
__device__ __forceinline__ int pperm(int c7) { return ((c7 & 3) << 1) | (c7 >> 2); }

__device__ __forceinline__ void mma_tf32(float* c,
                                         uint32_t a0, uint32_t a1, uint32_t a2, uint32_t a3,
                                         uint32_t b0, uint32_t b1) {
    asm volatile(
        "mma.sync.aligned.m16n8k8.row.col.f32.tf32.tf32.f32 "
        "{%0,%1,%2,%3}, {%4,%5,%6,%7}, {%8,%9}, {%0,%1,%2,%3};\n"
        : "+f"(c[0]), "+f"(c[1]), "+f"(c[2]), "+f"(c[3])
        : "r"(a0), "r"(a1), "r"(a2), "r"(a3), "r"(b0), "r"(b1));
}

__device__ __forceinline__ void cp_async16(uint32_t smem_addr, const void* gptr) {
    asm volatile("cp.async.ca.shared.global [%0], [%1], 16;\n"
                 :: "r"(smem_addr), "l"(gptr));
}
__device__ __forceinline__ void cp_commit() { asm volatile("cp.async.commit_group;\n"); }
__device__ __forceinline__ void cp_wait0() { asm volatile("cp.async.wait_group 0;\n"); }

// ---------------------------------------------------------------------------
// Convert x (f32 row-major [64][H]) -> g_xt tile image (tf32, permuted, padded)
// ---------------------------------------------------------------------------
__global__ void xcvt_kernel(const float* __restrict__ x) {
    const int c = blockIdx.x * 256 + threadIdx.x;   // 0..H-1
    const int m = blockIdx.y;                       // 0..63
    const int tile = c >> 6, cc = c & 63;
    const int ks = cc >> 3, c7 = cc & 7;
    g_xt[(tile * 64 + m) * 72 + ks * 8 + pperm(c7)] = f2tf32(x[m * H_DIM + c]);
}

// ---------------------------------------------------------------------------
// h = silu(gate)*up (reducing GU_SPLIT partials), emitted as tf32 tile image
// ---------------------------------------------------------------------------
__global__ void silu_kernel() {
    const int c = blockIdx.x * 256 + threadIdx.x;   // 0..I-1
    const int m = blockIdx.y;
    const long idx = (long)m * I_DIM + c;
    const long sl = (long)B_DIM * I_DIM;
    float gv = 0.f, uv = 0.f;
#pragma unroll
    for (int z = 0; z < GU_SPLIT; ++z) {
        gv += g_pg[z * sl + idx];
        uv += g_pu[z * sl + idx];
    }
    const float h = gv * uv / (1.f + __expf(-gv));
    const int tile = c >> 6, cc = c & 63;
    const int ks = cc >> 3, c7 = cc & 7;
    g_ht[(tile * 64 + m) * 72 + ks * 8 + pperm(c7)] = f2tf32(h);
}

// out = sum of DN_SPLIT down partials
__global__ void add_kernel(float* __restrict__ out) {
    const int i = blockIdx.x * blockDim.x + threadIdx.x;
    float v = 0.f;
#pragma unroll
    for (int z = 0; z < DN_SPLIT; ++z) v += g_pd[z * (B_DIM * H_DIM) + i];
    out[i] = v;
}

// ---------------------------------------------------------------------------
// W4A16 GEMM: outp[s][64, Ntot] = X[64, Kslice] * dequant(Wq)^T
// CTA tile 64(batch) x 128(wout) x 64(k); 4 warps of 32x64 (2m x 2n).
// Cuts L1 bytes/output 25% vs 64x64: 12 LDS.64 feed 16 MMAs per ks.
// X via cp.async from tile image; W dequantized in registers
// (I2F + FFMA(q,s,-z*s) + CVT), one row per thread. Double-buffered smem,
// one __syncthreads per K iter, A-fragments register-double-buffered.
// grid.x = n_tiles * split (uniform split-K); blockIdx.z selects weight set.
// ---------------------------------------------------------------------------
__global__ __launch_bounds__(128, 2) void gemm_w4(
    const uint32_t* __restrict__ Xt,   // tile image, tile-major
    const int* __restrict__ qA, const float* __restrict__ scA, const float* __restrict__ zrA,
    float* __restrict__ opA,
    const int* __restrict__ qB, const float* __restrict__ scB, const float* __restrict__ zrB,
    float* __restrict__ opB,
    int Kdim, int ng, int Ntot, int split)
{
    const int* q; const float* sc; const float* zr; float* outp;
    if (blockIdx.z == 0) { q = qA; sc = scA; zr = zrA; outp = opA; }
    else                 { q = qB; sc = scB; zr = zrB; outp = opB; }

    extern __shared__ uint32_t smem[];
    uint32_t* sX = smem;                 // [2][64*72]
    uint32_t* sW = smem + 2 * TX_WORDS;  // [2][128*72]
    const uint32_t sXu = (uint32_t)__cvta_generic_to_shared(sX);

    const int tid  = threadIdx.x;
    const int warp = tid >> 5;
    const int lane = tid & 31;
    const int qg   = lane >> 2;
    const int qt   = lane & 3;
    const int m0w  = (warp & 1) * 32;       // batch rows of this warp
    const int n0w  = (warp >> 1) * 64;      // wout cols of this warp

    const int n_t = blockIdx.x / split;
    const int s   = blockIdx.x % split;
    const int n0  = n_t * 128;

    // uneven split-K by k-tile index (64-tile boundaries are group-aligned)
    const int T    = Kdim >> 6;
    const int t_lo = (T * s) / split;
    const int t_hi = (T * (s + 1)) / split;
    const int NT   = t_hi - t_lo;
    const int kbeg = t_lo << 6;

    const int ln = tid;                    // W loader: one 128-row per thread
    const long wrow = (long)(n0 + ln) * Kdim;

    float acc[2][8][4];
#pragma unroll
    for (int mi = 0; mi < 2; ++mi)
#pragma unroll
        for (int j = 0; j < 8; ++j)
#pragma unroll
            for (int i = 0; i < 4; ++i) acc[mi][j][i] = 0.f;

    int4  wq[16];            // one full W row (64 int codes)
    float s0, zs0;           // zs = -z*s per row-tile

    auto load_w = [&](int k) {
        const int gk = kbeg + k * 64;
        const int gi = gk >> 7;
        s0 = sc[(n0 + ln) * ng + gi];
        zs0 = -zr[(n0 + ln) * ng + gi] * s0;
        const int4* p = (const int4*)(q + wrow + gk);
#pragma unroll
        for (int i = 0; i < 16; ++i) wq[i] = p[i];
    };

    auto dq1 = [&](int v, float sv, float zs) -> uint32_t {
        return f2tf32(fmaf((float)v, sv, zs));
    };

    auto stage_w = [&](int buf) {
        uint32_t* d = &sW[buf + ln * 72];
#pragma unroll
        for (int g = 0; g < 8; ++g) {   // 8-col k-group, pair-permuted
            const int4 A = wq[2 * g], B = wq[2 * g + 1];
            ((uint4*)(d + g * 8))[0] = make_uint4(dq1(A.x, s0, zs0), dq1(B.x, s0, zs0),
                                                  dq1(A.y, s0, zs0), dq1(B.y, s0, zs0));
            ((uint4*)(d + g * 8))[1] = make_uint4(dq1(A.z, s0, zs0), dq1(B.z, s0, zs0),
                                                  dq1(A.w, s0, zs0), dq1(B.w, s0, zs0));
        }
    };

    // cp.async one X tile image (1152 x 16B chunks) into buffer
    auto fetch_x = [&](int k, int buf_bytes) {
        const char* src = (const char*)(Xt + (long)(t_lo + k) * TX_WORDS);
#pragma unroll
        for (int j = 0; j < 9; ++j) {
            const int off = (j * 128 + tid) * 16;
            cp_async16(sXu + buf_bytes + off, src + off);
        }
        cp_commit();
    };

    // ---- prologue: X(0)+W(0) -> buf0, W(1) -> regs ----
    fetch_x(0, 0);
    load_w(0);
    stage_w(0);
    if (NT > 1) load_w(1);
    cp_wait0();
    __syncthreads();

    for (int k = 0; k < NT; ++k) {
        const int curX = (k & 1) * TX_WORDS, curW = (k & 1) * TW_WORDS;
        const int nxtX = ((k + 1) & 1) * TX_WORDS, nxtW = ((k + 1) & 1) * TW_WORDS;

        if (k + 1 < NT) {
            fetch_x(k + 1, nxtX * 4);   // into buffer retired at last barrier
            stage_w(nxtW);              // consumes wq(k+1) loaded last iter
        }
        if (k + 2 < NT) load_w(k + 2);  // LDG 2 iters ahead (after stage_w)

        // ---- MMA with A-fragment register double-buffering across ks ----
        uint2 fa[2][4];
        {
            const int kk0 = 2 * qt;
            fa[0][0] = *(const uint2*)&sX[curX + (m0w + qg)      * 72 + kk0];
            fa[0][1] = *(const uint2*)&sX[curX + (m0w + qg + 8)  * 72 + kk0];
            fa[0][2] = *(const uint2*)&sX[curX + (m0w + qg + 16) * 72 + kk0];
            fa[0][3] = *(const uint2*)&sX[curX + (m0w + qg + 24) * 72 + kk0];
        }
#pragma unroll
        for (int ks = 0; ks < 8; ++ks) {
            const int kk = ks * 8 + 2 * qt;
            const int pc = ks & 1, pn = pc ^ 1;
            if (ks < 7) {
                const int kk1 = kk + 8;
                fa[pn][0] = *(const uint2*)&sX[curX + (m0w + qg)      * 72 + kk1];
                fa[pn][1] = *(const uint2*)&sX[curX + (m0w + qg + 8)  * 72 + kk1];
                fa[pn][2] = *(const uint2*)&sX[curX + (m0w + qg + 16) * 72 + kk1];
                fa[pn][3] = *(const uint2*)&sX[curX + (m0w + qg + 24) * 72 + kk1];
            }
#pragma unroll
            for (int j = 0; j < 8; ++j) {
                uint2 bb = *(const uint2*)&sW[curW + (n0w + j * 8 + qg) * 72 + kk];
                mma_tf32(acc[0][j], fa[pc][0].x, fa[pc][1].x, fa[pc][0].y, fa[pc][1].y, bb.x, bb.y);
                mma_tf32(acc[1][j], fa[pc][2].x, fa[pc][3].x, fa[pc][2].y, fa[pc][3].y, bb.x, bb.y);
            }
        }
        cp_wait0();       // X(k+1) landed (had the whole MMA block to fly)
        __syncthreads();  // publishes X(k+1)+W(k+1); retires reads of cur
    }

    float* ob = outp + (long)s * (B_DIM * (long)Ntot);
#pragma unroll
    for (int mi = 0; mi < 2; ++mi)
#pragma unroll
        for (int j = 0; j < 8; ++j) {
            const int row = m0w + mi * 16 + qg;         // batch row
            const int col = n0 + n0w + j * 8 + qt * 2;  // wout col
            *(float2*)&ob[(long)row * Ntot + col] =
                make_float2(acc[mi][j][0], acc[mi][j][1]);
            *(float2*)&ob[(long)(row + 8) * Ntot + col] =
                make_float2(acc[mi][j][2], acc[mi][j][3]);
        }
}

// ---------------------------------------------------------------------------
extern "C" void kernel_launch(void* const* d_in, const int* in_sizes, int n_in,
                              void* d_out, int out_size) {
    (void)in_sizes; (void)n_in; (void)out_size;
    const float* x  = (const float*)d_in[0];
    const int*   gq = (const int*)d_in[1];
    const float* gs = (const float*)d_in[2];
    const float* gz = (const float*)d_in[3];
    const int*   uq = (const int*)d_in[4];
    const float* us = (const float*)d_in[5];
    const float* uz = (const float*)d_in[6];
    const int*   dq = (const int*)d_in[7];
    const float* ds = (const float*)d_in[8];
    const float* dz = (const float*)d_in[9];
    float* out = (float*)d_out;

    // Unconditional (no static guards); idempotent and capture-safe.
    cudaFuncSetAttribute(gemm_w4, cudaFuncAttributeMaxDynamicSharedMemorySize, SMEM_BYTES);

    uint32_t* xt; cudaGetSymbolAddress((void**)&xt, g_xt);
    uint32_t* ht; cudaGetSymbolAddress((void**)&ht, g_ht);
    float* pg; cudaGetSymbolAddress((void**)&pg, g_pg);
    float* pu; cudaGetSymbolAddress((void**)&pu, g_pu);
    float* pd; cudaGetSymbolAddress((void**)&pd, g_pd);

    xcvt_kernel<<<dim3(H_DIM / 256, B_DIM), 256>>>(x);

    // gate + up: 86 n-tiles x 5 splits x 2 matrices = 860 CTAs
    // = 2.9 waves at occ 2 (296 slots), 8 warps/SM.
    gemm_w4<<<dim3((I_DIM / 128) * GU_SPLIT, 1, 2), 128, SMEM_BYTES>>>(
        xt, gq, gs, gz, pg, uq, us, uz, pu,
        H_DIM, H_DIM / QGROUP, I_DIM, GU_SPLIT);

    silu_kernel<<<dim3(I_DIM / 256, B_DIM), 256>>>();

    // down: 32 n-tiles x 9 splits = 288 CTAs ~ 0.97 occ-2 wave.
    gemm_w4<<<dim3((H_DIM / 128) * DN_SPLIT, 1, 1), 128, SMEM_BYTES>>>(
        ht, dq, ds, dz, pd, dq, ds, dz, pd,
        I_DIM, I_DIM / QGROUP, H_DIM, DN_SPLIT);

    add_kernel<<<(B_DIM * H_DIM) / 512, 512>>>(out);
}